// round 3
// baseline (speedup 1.0000x reference)
#include <cuda_runtime.h>

// ---------------------------------------------------------------------------
// Problem constants
// ---------------------------------------------------------------------------
#define Bv   16
#define Kv   1024
#define Dv   256
#define HIDv 256
#define Hv   4
#define DKv  64
#define Mrows (Bv * Kv)            // 16384 rows of the token matrix

static const size_t ADJ_ELEMS = (size_t)Bv * 5 * Kv * Kv;   // 83,886,080

// ---------------------------------------------------------------------------
// Device scratch (static globals; no allocation allowed)
// sup1/h1 layout: [m][1024]  with columns = pair p*512 + h2*256 + f
// sup2/h2c layout: [m][256]  with columns = pair p*128 + h2*64 + e
// ---------------------------------------------------------------------------
__device__ float d_sup1[(size_t)Mrows * 1024];
__device__ float d_h1  [(size_t)Mrows * 1024];
__device__ float d_sup2[(size_t)Mrows * 256];
__device__ float d_h2c [(size_t)Mrows * 256];
__device__ float d_g   [(size_t)Mrows * 256];
__device__ float d_ff1 [(size_t)Mrows * 256];
__device__ float d_Wc1 [256 * 1024];   // packed layer-1 weights [d][p*512+h2*256+f]
__device__ float d_bc1 [1024];
__device__ float d_bc2 [256];

// ---------------------------------------------------------------------------
// adj passthrough: int32 -> float32 (vectorized)
// ---------------------------------------------------------------------------
__global__ void conv_adj(const int* __restrict__ g, float* __restrict__ o, int n4) {
    int i = blockIdx.x * blockDim.x + threadIdx.x;
    if (i < n4) {
        int4 v = ((const int4*)g)[i];
        float4 f = make_float4((float)v.x, (float)v.y, (float)v.z, (float)v.w);
        ((float4*)o)[i] = f;
    }
}

// ---------------------------------------------------------------------------
// Weight / bias packing for pair-fused layer-1
// ---------------------------------------------------------------------------
__global__ void pack_w(const float* __restrict__ Wg1, const float* __restrict__ bg1,
                       const float* __restrict__ bg2) {
    int i = blockIdx.x * blockDim.x + threadIdx.x;
    if (i < 256 * 1024) {
        int d = i >> 10;  int c = i & 1023;
        int p = c >> 9;   int r = c & 511;
        int h2 = r >> 8;  int f = r & 255;
        d_Wc1[i] = Wg1[(((p * 2 + h2) * 256) + d) * 256 + f];
    }
    if (i < 1024) {
        int p = i >> 9; int r = i & 511; int h2 = r >> 8; int f = r & 255;
        d_bc1[i] = bg1[(p * 2 + h2) * 256 + f];
    }
    if (i < 256) {
        int p = i >> 7; int r = i & 127; int h2 = r >> 6; int e = r & 63;
        d_bc2[i] = bg2[(p * 2 + h2) * 64 + e];
    }
}

// ---------------------------------------------------------------------------
// Generic fp32 tiled GEMM:  C = act(A @ W + bias) (+ res)
// BM=128, BN=64, BK=16, 256 threads, 8x4 microtile.
// gridDim.z batches with element strides sAz/sWz/sCz.
// ---------------------------------------------------------------------------
#define BM 128
#define BN 64
#define BKt 16

template<bool RELU, bool RES>
__global__ __launch_bounds__(256)
void gemm_k(const float* __restrict__ A, int lda, long long sAz,
            const float* __restrict__ W, int ldw, long long sWz,
            const float* __restrict__ bias,
            const float* __restrict__ res, int ldres,
            float* __restrict__ C, int ldc, long long sCz,
            int Kd)
{
    __shared__ __align__(16) float As[BKt][BM];
    __shared__ __align__(16) float Bs[BKt][BN];
    const int tid = threadIdx.x;
    const int bm = blockIdx.y * BM;
    const int bn = blockIdx.x * BN;
    const long long z = blockIdx.z;
    A += z * sAz;  W += z * sWz;  C += z * sCz;

    const int ty = tid >> 4;      // 0..15 -> row group of 8
    const int tx = tid & 15;      // 0..15 -> col group of 4
    float acc[8][4] = {};

    for (int k0 = 0; k0 < Kd; k0 += BKt) {
        // Load A tile (128x16) : 512 float4, 2 per thread
        #pragma unroll
        for (int i = 0; i < 2; i++) {
            int idx = tid * 2 + i;
            int r   = idx >> 2;
            int k4  = (idx & 3) << 2;
            const float4 v = *(const float4*)(A + (size_t)(bm + r) * lda + k0 + k4);
            As[k4 + 0][r] = v.x;  As[k4 + 1][r] = v.y;
            As[k4 + 2][r] = v.z;  As[k4 + 3][r] = v.w;
        }
        // Load B tile (16x64) : 256 float4, 1 per thread
        {
            int kr = tid >> 4;
            int n4 = (tid & 15) << 2;
            *(float4*)&Bs[kr][n4] = *(const float4*)(W + (size_t)(k0 + kr) * ldw + bn + n4);
        }
        __syncthreads();
        #pragma unroll
        for (int k = 0; k < BKt; k++) {
            float4 a0 = *(const float4*)&As[k][ty * 8];
            float4 a1 = *(const float4*)&As[k][ty * 8 + 4];
            float4 b0 = *(const float4*)&Bs[k][tx * 4];
            float av[8] = {a0.x, a0.y, a0.z, a0.w, a1.x, a1.y, a1.z, a1.w};
            float bv[4] = {b0.x, b0.y, b0.z, b0.w};
            #pragma unroll
            for (int i = 0; i < 8; i++)
                #pragma unroll
                for (int j = 0; j < 4; j++)
                    acc[i][j] += av[i] * bv[j];
        }
        __syncthreads();
    }

    const int col = bn + tx * 4;
    float4 bb = make_float4(0.f, 0.f, 0.f, 0.f);
    if (bias) bb = *(const float4*)(bias + col);
    #pragma unroll
    for (int i = 0; i < 8; i++) {
        int row = bm + ty * 8 + i;
        float4 o = make_float4(acc[i][0] + bb.x, acc[i][1] + bb.y,
                               acc[i][2] + bb.z, acc[i][3] + bb.w);
        if (RELU) {
            o.x = fmaxf(o.x, 0.f); o.y = fmaxf(o.y, 0.f);
            o.z = fmaxf(o.z, 0.f); o.w = fmaxf(o.w, 0.f);
        }
        if (RES) {
            float4 r4 = *(const float4*)(res + (size_t)row * ldres + col);
            o.x += r4.x; o.y += r4.y; o.z += r4.z; o.w += r4.w;
        }
        *(float4*)(C + (size_t)row * ldc + col) = o;
    }
}

// ---------------------------------------------------------------------------
// Adjacency GEMM:  C[p,b] = act(adj[b,slice(p)] @ Bmat[p,b] + bias[p])
// blockIdx.z = p*16 + b. M=1024, inner=1024 fixed, Nloc in {512,128}.
// Adjacency loaded as int4 and converted (values are exactly 0/1).
// ---------------------------------------------------------------------------
template<bool RELU>
__global__ __launch_bounds__(256)
void adj_gemm(const int* __restrict__ graph, const float* __restrict__ Bmat, int ldb,
              const float* __restrict__ bias, float* __restrict__ Cmat, int Nloc)
{
    const int z = blockIdx.z;
    const int p = z >> 4;
    const int b = z & 15;
    const int slice = p ? 4 : 1;
    const int*   A  = graph + ((size_t)(b * 5 + slice)) * Kv * Kv;
    const float* Bp = Bmat + (size_t)b * Kv * ldb + p * Nloc;
    float*       Cp = Cmat + (size_t)b * Kv * ldb + p * Nloc;
    const float* bp = bias + p * Nloc;

    __shared__ __align__(16) float As[BKt][BM];
    __shared__ __align__(16) float Bs[BKt][BN];
    const int tid = threadIdx.x;
    const int bm = blockIdx.y * BM;
    const int bn = blockIdx.x * BN;
    const int ty = tid >> 4;
    const int tx = tid & 15;
    float acc[8][4] = {};

    for (int k0 = 0; k0 < Kv; k0 += BKt) {
        #pragma unroll
        for (int i = 0; i < 2; i++) {
            int idx = tid * 2 + i;
            int r   = idx >> 2;
            int k4  = (idx & 3) << 2;
            const int4 v = *(const int4*)(A + (size_t)(bm + r) * Kv + k0 + k4);
            As[k4 + 0][r] = (float)v.x;  As[k4 + 1][r] = (float)v.y;
            As[k4 + 2][r] = (float)v.z;  As[k4 + 3][r] = (float)v.w;
        }
        {
            int kr = tid >> 4;
            int n4 = (tid & 15) << 2;
            *(float4*)&Bs[kr][n4] = *(const float4*)(Bp + (size_t)(k0 + kr) * ldb + bn + n4);
        }
        __syncthreads();
        #pragma unroll
        for (int k = 0; k < BKt; k++) {
            float4 a0 = *(const float4*)&As[k][ty * 8];
            float4 a1 = *(const float4*)&As[k][ty * 8 + 4];
            float4 b0 = *(const float4*)&Bs[k][tx * 4];
            float av[8] = {a0.x, a0.y, a0.z, a0.w, a1.x, a1.y, a1.z, a1.w};
            float bv[4] = {b0.x, b0.y, b0.z, b0.w};
            #pragma unroll
            for (int i = 0; i < 8; i++)
                #pragma unroll
                for (int j = 0; j < 4; j++)
                    acc[i][j] += av[i] * bv[j];
        }
        __syncthreads();
    }

    const int col = bn + tx * 4;
    const float4 bb = *(const float4*)(bp + col);
    #pragma unroll
    for (int i = 0; i < 8; i++) {
        int row = bm + ty * 8 + i;
        float4 o = make_float4(acc[i][0] + bb.x, acc[i][1] + bb.y,
                               acc[i][2] + bb.z, acc[i][3] + bb.w);
        if (RELU) {
            o.x = fmaxf(o.x, 0.f); o.y = fmaxf(o.y, 0.f);
            o.z = fmaxf(o.z, 0.f); o.w = fmaxf(o.w, 0.f);
        }
        *(float4*)(Cp + (size_t)row * ldb + col) = o;
    }
}

// ---------------------------------------------------------------------------
// LayerNorm (MWPToolkit: a*(x-mu)/(std_ddof1 + eps) + b) + residual
// One warp per 256-wide row.
// ---------------------------------------------------------------------------
__global__ __launch_bounds__(256)
void ln_kernel(const float* __restrict__ x, const float* __restrict__ nodes,
               const float* __restrict__ ln_a, const float* __restrict__ ln_b,
               float* __restrict__ g)
{
    int warp = (blockIdx.x * blockDim.x + threadIdx.x) >> 5;
    int lane = threadIdx.x & 31;
    if (warp >= Mrows) return;
    const float* xr = x + (size_t)warp * 256;
    float v[8];
    float s = 0.f, ss = 0.f;
    #pragma unroll
    for (int j = 0; j < 8; j++) {
        v[j] = xr[lane + j * 32];
        s += v[j];
        ss += v[j] * v[j];
    }
    #pragma unroll
    for (int o = 16; o; o >>= 1) {
        s  += __shfl_xor_sync(0xffffffffu, s, o);
        ss += __shfl_xor_sync(0xffffffffu, ss, o);
    }
    float mu  = s * (1.f / 256.f);
    float var = (ss - 256.f * mu * mu) * (1.f / 255.f);
    float inv = 1.f / (sqrtf(fmaxf(var, 0.f)) + 1e-6f);
    const float* nd = nodes + (size_t)warp * 256;
    float* go = g + (size_t)warp * 256;
    #pragma unroll
    for (int j = 0; j < 8; j++) {
        int c = lane + j * 32;
        go[c] = ln_a[c] * (v[j] - mu) * inv + ln_b[c] + nd[c];
    }
}

// ---------------------------------------------------------------------------
// Launcher
// ---------------------------------------------------------------------------
extern "C" void kernel_launch(void* const* d_in, const int* in_sizes, int n_in,
                              void* d_out, int out_size)
{
    const float* nodes = (const float*)d_in[0];
    const int*   graph = (const int*)d_in[1];
    const float* Wg1   = (const float*)d_in[2];
    const float* bg1   = (const float*)d_in[3];
    const float* Wg2   = (const float*)d_in[4];
    const float* bg2   = (const float*)d_in[5];
    const float* Wf1   = (const float*)d_in[6];
    const float* bf1   = (const float*)d_in[7];
    const float* Wf2   = (const float*)d_in[8];
    const float* bf2   = (const float*)d_in[9];
    const float* ln_a  = (const float*)d_in[10];
    const float* ln_b  = (const float*)d_in[11];
    float* out = (float*)d_out;

    float *sup1, *h1, *sup2, *h2c, *g, *ff1, *Wc1, *bc1, *bc2;
    cudaGetSymbolAddress((void**)&sup1, d_sup1);
    cudaGetSymbolAddress((void**)&h1,   d_h1);
    cudaGetSymbolAddress((void**)&sup2, d_sup2);
    cudaGetSymbolAddress((void**)&h2c,  d_h2c);
    cudaGetSymbolAddress((void**)&g,    d_g);
    cudaGetSymbolAddress((void**)&ff1,  d_ff1);
    cudaGetSymbolAddress((void**)&Wc1,  d_Wc1);
    cudaGetSymbolAddress((void**)&bc1,  d_bc1);
    cudaGetSymbolAddress((void**)&bc2,  d_bc2);

    // 0) adj passthrough (int -> float), 20,971,520 float4s
    conv_adj<<<81920, 256>>>(graph, out, (int)(ADJ_ELEMS / 4));

    // 1) weight packing (tiny)
    pack_w<<<1024, 256>>>(Wg1, bg1, bg2);

    // 2) sup1 = nodes @ Wc1            (16384 x 256) @ (256 x 1024)
    gemm_k<false, false><<<dim3(16, 128, 1), 256>>>(
        nodes, 256, 0, Wc1, 1024, 0, nullptr, nullptr, 0, sup1, 1024, 0, 256);

    // 3) h1 = relu(adj @ sup1 + bc1)   32 batches of (1024x1024)@(1024x512)
    adj_gemm<true><<<dim3(8, 8, 32), 256>>>(graph, sup1, 1024, bc1, h1, 512);

    // 4) sup2 = h1 @ Wg2 (block-diag per head, batched over z=h)
    gemm_k<false, false><<<dim3(1, 128, 4), 256>>>(
        h1, 1024, 256, Wg2, 64, (long long)256 * 64, nullptr, nullptr, 0,
        sup2, 256, 64, 256);

    // 5) h2 = adj @ sup2 + bc2         32 batches of (1024x1024)@(1024x128)
    adj_gemm<false><<<dim3(2, 8, 32), 256>>>(graph, sup2, 256, bc2, h2c, 128);

    // 6) g = LN(h2cat) + nodes
    ln_kernel<<<2048, 256>>>(h2c, nodes, ln_a, ln_b, g);

    // 7) ff1 = relu(g @ Wf1 + bf1)
    gemm_k<true, false><<<dim3(4, 128, 1), 256>>>(
        g, 256, 0, Wf1, 256, 0, bf1, nullptr, 0, ff1, 256, 0, 256);

    // 8) out = ff1 @ Wf2 + bf2 + g
    gemm_k<false, true><<<dim3(4, 128, 1), 256>>>(
        ff1, 256, 0, Wf2, 256, 0, bf2, g, 256, out + ADJ_ELEMS, 256, 0, 256);
}

// round 5
// speedup vs baseline: 1.8960x; 1.8960x over previous
#include <cuda_runtime.h>
#include <cstdint>

// ---------------------------------------------------------------------------
// Problem constants
// ---------------------------------------------------------------------------
#define Bv   16
#define Kv   1024
#define Mrows (Bv * Kv)            // 16384 rows of the token matrix

static const size_t ADJ_ELEMS = (size_t)Bv * 5 * Kv * Kv;   // 83,886,080

// ---------------------------------------------------------------------------
// Device scratch
// ---------------------------------------------------------------------------
__device__ float d_sup1[(size_t)Mrows * 1024];
__device__ float d_h1  [(size_t)Mrows * 1024];
__device__ float d_sup2[(size_t)Mrows * 256];
__device__ float d_h2c [(size_t)Mrows * 256];
__device__ float d_g   [(size_t)Mrows * 256];
__device__ float d_ff1 [(size_t)Mrows * 256];
__device__ float d_Wc1 [256 * 1024];   // packed layer-1 weights
__device__ float d_bc1 [1024];
__device__ float d_bc2 [256];

// ---------------------------------------------------------------------------
// adj passthrough: int32 -> float32 (vectorized)
// ---------------------------------------------------------------------------
__global__ void conv_adj(const int* __restrict__ g, float* __restrict__ o, int n4) {
    int i = blockIdx.x * blockDim.x + threadIdx.x;
    if (i < n4) {
        int4 v = ((const int4*)g)[i];
        ((float4*)o)[i] = make_float4((float)v.x, (float)v.y, (float)v.z, (float)v.w);
    }
}

// ---------------------------------------------------------------------------
// Weight / bias packing for pair-fused layer-1
// ---------------------------------------------------------------------------
__global__ void pack_w(const float* __restrict__ Wg1, const float* __restrict__ bg1,
                       const float* __restrict__ bg2) {
    int i = blockIdx.x * blockDim.x + threadIdx.x;
    if (i < 256 * 1024) {
        int d = i >> 10;  int c = i & 1023;
        int p = c >> 9;   int r = c & 511;
        int h2 = r >> 8;  int f = r & 255;
        d_Wc1[i] = Wg1[(((p * 2 + h2) * 256) + d) * 256 + f];
    }
    if (i < 1024) {
        int p = i >> 9; int r = i & 511; int h2 = r >> 8; int f = r & 255;
        d_bc1[i] = bg1[(p * 2 + h2) * 256 + f];
    }
    if (i < 256) {
        int p = i >> 7; int r = i & 127; int h2 = r >> 6; int e = r & 63;
        d_bc2[i] = bg2[(p * 2 + h2) * 64 + e];
    }
}

// ---------------------------------------------------------------------------
// tf32 helpers
// ---------------------------------------------------------------------------
__device__ __forceinline__ uint32_t f2tf(float x) {
    uint32_t r;
    asm("cvt.rna.tf32.f32 %0, %1;" : "=r"(r) : "f"(x));
    return r;
}

__device__ __forceinline__ void mma8(float* c, const uint32_t* a, const uint32_t* b) {
    asm volatile(
        "mma.sync.aligned.m16n8k8.row.col.f32.tf32.tf32.f32 "
        "{%0,%1,%2,%3},{%4,%5,%6,%7},{%8,%9},{%0,%1,%2,%3};"
        : "+f"(c[0]), "+f"(c[1]), "+f"(c[2]), "+f"(c[3])
        : "r"(a[0]), "r"(a[1]), "r"(a[2]), "r"(a[3]), "r"(b[0]), "r"(b[1]));
}

// ---------------------------------------------------------------------------
// tf32 tensor-core GEMM.  BM=128, BN=64, BK=32. 256 threads (8 warps, 4x2).
// Warp tile 32x32 = 2x4 m16n8k8 MMAs.
// A stored k-major in smem, stride 136 -> bank = (8k+m)%32, conflict-free frags.
// B stored k-major, stride 72 -> bank = (8k+n)%32, conflict-free frags.
// ADJ mode: blockIdx.z = p*16 + b, A = graph adjacency slice (int 0/1),
//           B/C/bias column-offset by p*Nloc.
// ---------------------------------------------------------------------------
#define AS_STRIDE 136
#define BS_STRIDE 72

template<bool ADJ, bool RELU, bool RES>
__global__ __launch_bounds__(256)
void tf32_gemm(const void* __restrict__ Av, int lda, long long sAz,
               const float* __restrict__ W, int ldw, long long sWz,
               const float* __restrict__ bias,
               const float* __restrict__ res, int ldres,
               float* __restrict__ C, int ldc, long long sCz,
               int Kd, int Nloc)
{
    __shared__ uint32_t As [32 * AS_STRIDE];
    __shared__ uint32_t Bsm[32 * BS_STRIDE];

    const int tid  = threadIdx.x;
    const int lane = tid & 31;
    const int wid  = tid >> 5;
    const int warp_m = wid & 3;        // 4 warps over M (32 rows each)
    const int warp_n = wid >> 2;       // 2 warps over N (32 cols each)
    const int bm = blockIdx.y * 128;
    const int bn = blockIdx.x * 64;
    const long long z = blockIdx.z;

    const int*   Ai = nullptr;
    const float* Af = nullptr;
    const float* Wp;
    float*       Cp;
    const float* bp = nullptr;
    const float* rp = nullptr;

    if (ADJ) {
        const int p = (int)(z >> 4);
        const int b = (int)(z & 15);
        const int slice = p ? 4 : 1;
        Ai = ((const int*)Av) + ((size_t)(b * 5 + slice)) * Kv * Kv;
        Wp = W + (size_t)b * Kv * ldw + p * Nloc;
        Cp = C + (size_t)b * Kv * ldc + p * Nloc;
        bp = bias + p * Nloc;
        Kd = Kv;
    } else {
        Af = ((const float*)Av) + z * sAz;
        Wp = W + z * sWz;
        Cp = C + z * sCz;
        bp = bias;
        if (RES) rp = res;
    }

    // global->reg staging assignment
    const int am  = tid >> 1;          // 0..127 : A row within tile
    const int akh = (tid & 1) * 16;    // k half: 0 or 16
    const int bkr = tid >> 4;          // 0..15  : B k row (and +16)
    const int bn4 = (tid & 15) * 4;    // B col chunk

    float4 areg[4];
    float4 breg[2];

    auto loadg = [&](int k0) {
        if (ADJ) {
            const int4* ap = reinterpret_cast<const int4*>(
                Ai + (size_t)(bm + am) * lda + k0 + akh);
            #pragma unroll
            for (int i = 0; i < 4; i++) {
                int4 v = ap[i];
                areg[i] = make_float4((float)v.x, (float)v.y, (float)v.z, (float)v.w);
            }
        } else {
            const float4* ap = reinterpret_cast<const float4*>(
                Af + (size_t)(bm + am) * lda + k0 + akh);
            #pragma unroll
            for (int i = 0; i < 4; i++) areg[i] = ap[i];
        }
        const float* wrow = Wp + (size_t)(k0 + bkr) * ldw + bn + bn4;
        breg[0] = *reinterpret_cast<const float4*>(wrow);
        breg[1] = *reinterpret_cast<const float4*>(wrow + (size_t)16 * ldw);
    };

    float acc[2][4][4] = {};

    loadg(0);
    const int niter = Kd / 32;

    for (int it = 0; it < niter; ++it) {
        __syncthreads();   // previous iteration's readers done
        // regs -> smem (rounded to tf32)
        #pragma unroll
        for (int i = 0; i < 4; i++) {
            int k = akh + 4 * i;
            As[(k + 0) * AS_STRIDE + am] = f2tf(areg[i].x);
            As[(k + 1) * AS_STRIDE + am] = f2tf(areg[i].y);
            As[(k + 2) * AS_STRIDE + am] = f2tf(areg[i].z);
            As[(k + 3) * AS_STRIDE + am] = f2tf(areg[i].w);
        }
        #pragma unroll
        for (int u = 0; u < 2; u++) {
            uint4 pv;
            pv.x = f2tf(breg[u].x); pv.y = f2tf(breg[u].y);
            pv.z = f2tf(breg[u].z); pv.w = f2tf(breg[u].w);
            *reinterpret_cast<uint4*>(&Bsm[(bkr + u * 16) * BS_STRIDE + bn4]) = pv;
        }
        __syncthreads();

        if (it + 1 < niter) loadg((it + 1) * 32);   // overlap LDG with MMAs

        #pragma unroll
        for (int kk = 0; kk < 4; kk++) {
            const int kA = kk * 8 + (lane & 3);
            uint32_t af[2][4], bf[4][2];
            #pragma unroll
            for (int mt = 0; mt < 2; mt++) {
                int r = warp_m * 32 + mt * 16 + (lane >> 2);
                af[mt][0] = As[kA * AS_STRIDE + r];
                af[mt][1] = As[kA * AS_STRIDE + r + 8];
                af[mt][2] = As[(kA + 4) * AS_STRIDE + r];
                af[mt][3] = As[(kA + 4) * AS_STRIDE + r + 8];
            }
            #pragma unroll
            for (int nt = 0; nt < 4; nt++) {
                int cc = warp_n * 32 + nt * 8 + (lane >> 2);
                bf[nt][0] = Bsm[kA * BS_STRIDE + cc];
                bf[nt][1] = Bsm[(kA + 4) * BS_STRIDE + cc];
            }
            #pragma unroll
            for (int mt = 0; mt < 2; mt++)
                #pragma unroll
                for (int nt = 0; nt < 4; nt++)
                    mma8(acc[mt][nt], af[mt], bf[nt]);
        }
    }

    // Epilogue
    #pragma unroll
    for (int mt = 0; mt < 2; mt++) {
        const int row = bm + warp_m * 32 + mt * 16 + (lane >> 2);
        #pragma unroll
        for (int nt = 0; nt < 4; nt++) {
            const int col = bn + warp_n * 32 + nt * 8 + 2 * (lane & 3);
            float b0 = 0.f, b1 = 0.f;
            if (bias) { b0 = bp[col]; b1 = bp[col + 1]; }
            float v0 = acc[mt][nt][0] + b0, v1 = acc[mt][nt][1] + b1;
            float v2 = acc[mt][nt][2] + b0, v3 = acc[mt][nt][3] + b1;
            if (RELU) {
                v0 = fmaxf(v0, 0.f); v1 = fmaxf(v1, 0.f);
                v2 = fmaxf(v2, 0.f); v3 = fmaxf(v3, 0.f);
            }
            if (RES) {
                const float* r0 = rp + (size_t)row * ldres + col;
                const float* r1 = rp + (size_t)(row + 8) * ldres + col;
                v0 += r0[0]; v1 += r0[1]; v2 += r1[0]; v3 += r1[1];
            }
            *reinterpret_cast<float2*>(&Cp[(size_t)row * ldc + col]) = make_float2(v0, v1);
            *reinterpret_cast<float2*>(&Cp[(size_t)(row + 8) * ldc + col]) = make_float2(v2, v3);
        }
    }
}

// ---------------------------------------------------------------------------
// LayerNorm (MWPToolkit: a*(x-mu)/(std_ddof1 + eps) + b) + residual
// ---------------------------------------------------------------------------
__global__ __launch_bounds__(256)
void ln_kernel(const float* __restrict__ x, const float* __restrict__ nodes,
               const float* __restrict__ ln_a, const float* __restrict__ ln_b,
               float* __restrict__ g)
{
    int warp = (blockIdx.x * blockDim.x + threadIdx.x) >> 5;
    int lane = threadIdx.x & 31;
    if (warp >= Mrows) return;
    const float* xr = x + (size_t)warp * 256;
    float v[8];
    float s = 0.f, ss = 0.f;
    #pragma unroll
    for (int j = 0; j < 8; j++) {
        v[j] = xr[lane + j * 32];
        s += v[j];
        ss += v[j] * v[j];
    }
    #pragma unroll
    for (int o = 16; o; o >>= 1) {
        s  += __shfl_xor_sync(0xffffffffu, s, o);
        ss += __shfl_xor_sync(0xffffffffu, ss, o);
    }
    float mu  = s * (1.f / 256.f);
    float var = (ss - 256.f * mu * mu) * (1.f / 255.f);
    float inv = 1.f / (sqrtf(fmaxf(var, 0.f)) + 1e-6f);
    const float* nd = nodes + (size_t)warp * 256;
    float* go = g + (size_t)warp * 256;
    #pragma unroll
    for (int j = 0; j < 8; j++) {
        int c = lane + j * 32;
        go[c] = ln_a[c] * (v[j] - mu) * inv + ln_b[c] + nd[c];
    }
}

// ---------------------------------------------------------------------------
// Launcher
// ---------------------------------------------------------------------------
extern "C" void kernel_launch(void* const* d_in, const int* in_sizes, int n_in,
                              void* d_out, int out_size)
{
    const float* nodes = (const float*)d_in[0];
    const int*   graph = (const int*)d_in[1];
    const float* Wg1   = (const float*)d_in[2];
    const float* bg1   = (const float*)d_in[3];
    const float* Wg2   = (const float*)d_in[4];
    const float* bg2   = (const float*)d_in[5];
    const float* Wf1   = (const float*)d_in[6];
    const float* bf1   = (const float*)d_in[7];
    const float* Wf2   = (const float*)d_in[8];
    const float* bf2   = (const float*)d_in[9];
    const float* ln_a  = (const float*)d_in[10];
    const float* ln_b  = (const float*)d_in[11];
    float* out = (float*)d_out;

    float *sup1, *h1, *sup2, *h2c, *g, *ff1, *Wc1, *bc1, *bc2;
    cudaGetSymbolAddress((void**)&sup1, d_sup1);
    cudaGetSymbolAddress((void**)&h1,   d_h1);
    cudaGetSymbolAddress((void**)&sup2, d_sup2);
    cudaGetSymbolAddress((void**)&h2c,  d_h2c);
    cudaGetSymbolAddress((void**)&g,    d_g);
    cudaGetSymbolAddress((void**)&ff1,  d_ff1);
    cudaGetSymbolAddress((void**)&Wc1,  d_Wc1);
    cudaGetSymbolAddress((void**)&bc1,  d_bc1);
    cudaGetSymbolAddress((void**)&bc2,  d_bc2);

    // 0) adj passthrough (int -> float)
    conv_adj<<<81920, 256>>>(graph, out, (int)(ADJ_ELEMS / 4));

    // 1) weight packing (tiny)
    pack_w<<<1024, 256>>>(Wg1, bg1, bg2);

    // 2) sup1 = nodes @ Wc1            (16384 x 256) @ (256 x 1024)
    tf32_gemm<false, false, false><<<dim3(16, 128, 1), 256>>>(
        nodes, 256, 0, Wc1, 1024, 0, nullptr, nullptr, 0,
        sup1, 1024, 0, 256, 0);

    // 3) h1 = relu(adj @ sup1 + bc1)   32 batches of (1024x1024)@(1024x512)
    tf32_gemm<true, true, false><<<dim3(8, 8, 32), 256>>>(
        graph, 1024, 0, sup1, 1024, 0, bc1, nullptr, 0,
        h1, 1024, 0, 1024, 512);

    // 4) sup2 = h1 @ Wg2 (block-diag per head, batched over z=h)
    tf32_gemm<false, false, false><<<dim3(1, 128, 4), 256>>>(
        h1, 1024, 256, Wg2, 64, (long long)256 * 64, nullptr, nullptr, 0,
        sup2, 256, 64, 256, 0);

    // 5) h2 = adj @ sup2 + bc2         32 batches of (1024x1024)@(1024x128)
    tf32_gemm<true, false, false><<<dim3(2, 8, 32), 256>>>(
        graph, 1024, 0, sup2, 256, 0, bc2, nullptr, 0,
        h2c, 256, 0, 1024, 128);

    // 6) g = LN(h2cat) + nodes
    ln_kernel<<<2048, 256>>>(h2c, nodes, ln_a, ln_b, g);

    // 7) ff1 = relu(g @ Wf1 + bf1)
    tf32_gemm<false, true, false><<<dim3(4, 128, 1), 256>>>(
        g, 256, 0, Wf1, 256, 0, bf1, nullptr, 0,
        ff1, 256, 0, 256, 0);

    // 8) out = ff1 @ Wf2 + bf2 + g
    tf32_gemm<false, false, true><<<dim3(4, 128, 1), 256>>>(
        ff1, 256, 0, Wf2, 256, 0, bf2, g, 256,
        out + ADJ_ELEMS, 256, 0, 256, 0);
}

// round 11
// speedup vs baseline: 2.7182x; 1.4336x over previous
#include <cuda_runtime.h>
#include <cstdint>

// ---------------------------------------------------------------------------
// Problem constants
// ---------------------------------------------------------------------------
#define Bv   16
#define Kv   1024
#define Mrows (Bv * Kv)            // 16384 rows of the token matrix

static const size_t ADJ_ELEMS = (size_t)Bv * 5 * Kv * Kv;   // 83,886,080

// ---------------------------------------------------------------------------
// Device scratch
// ---------------------------------------------------------------------------
__device__ float d_sup1[(size_t)Mrows * 1024];
__device__ float d_h1  [(size_t)Mrows * 1024];
__device__ float d_sup2[(size_t)Mrows * 256];
__device__ float d_h2c [(size_t)Mrows * 256];
__device__ float d_g   [(size_t)Mrows * 256];
__device__ float d_ff1 [(size_t)Mrows * 256];
__device__ float d_Wc1 [256 * 1024];   // packed layer-1 weights [k][p*512+h2*256+f]
__device__ float d_W2bd[1024 * 256];   // block-diagonal layer-2 weights
__device__ float d_bc1 [1024];
__device__ float d_bc2 [256];

// ---------------------------------------------------------------------------
// helpers
// ---------------------------------------------------------------------------
__device__ __forceinline__ uint32_t smem_to_u32(const void* p) {
    uint32_t a;
    asm("{ .reg .u64 t; cvta.to.shared.u64 t, %1; cvt.u32.u64 %0, t; }"
        : "=r"(a) : "l"(p));
    return a;
}

// tf32 rounding (RNA) so the MMA's truncating read is unbiased
__device__ __forceinline__ uint32_t f2tf(float x) {
    uint32_t r;
    asm("cvt.rna.tf32.f32 %0, %1;" : "=r"(r) : "f"(x));
    return r;
}

__device__ __forceinline__ void mma8(float* c, const uint32_t* a, const uint32_t* b) {
    asm volatile(
        "mma.sync.aligned.m16n8k8.row.col.f32.tf32.tf32.f32 "
        "{%0,%1,%2,%3},{%4,%5,%6,%7},{%8,%9},{%0,%1,%2,%3};"
        : "+f"(c[0]), "+f"(c[1]), "+f"(c[2]), "+f"(c[3])
        : "r"(a[0]), "r"(a[1]), "r"(a[2]), "r"(a[3]), "r"(b[0]), "r"(b[1]));
}

__device__ __forceinline__ void cp_async16(uint32_t dst, const void* src) {
    asm volatile("cp.async.ca.shared.global [%0], [%1], 16;"
                 :: "r"(dst), "l"(src) : "memory");
}
__device__ __forceinline__ void cp_commit() {
    asm volatile("cp.async.commit_group;" ::: "memory");
}
__device__ __forceinline__ void cp_wait0() {
    asm volatile("cp.async.wait_group 0;" ::: "memory");
}

// ---------------------------------------------------------------------------
// adj passthrough: int32 -> float32  (output doubles as fp32 adjacency source)
// ---------------------------------------------------------------------------
__global__ void conv_adj(const int* __restrict__ g, float* __restrict__ o, int n4) {
    int i = blockIdx.x * blockDim.x + threadIdx.x;
    if (i < n4) {
        int4 v = ((const int4*)g)[i];
        ((float4*)o)[i] = make_float4((float)v.x, (float)v.y, (float)v.z, (float)v.w);
    }
}

// ---------------------------------------------------------------------------
// Weight / bias packing: pair-fused layer-1 + block-diagonal layer-2
// ---------------------------------------------------------------------------
__global__ void pack_w(const float* __restrict__ Wg1, const float* __restrict__ bg1,
                       const float* __restrict__ Wg2, const float* __restrict__ bg2) {
    int i = blockIdx.x * blockDim.x + threadIdx.x;
    if (i < 256 * 1024) {
        int d = i >> 10;  int c = i & 1023;
        int p = c >> 9;   int r = c & 511;
        int h2 = r >> 8;  int f = r & 255;
        d_Wc1[i] = Wg1[(((p * 2 + h2) * 256) + d) * 256 + f];

        int j = i >> 8;  int n = i & 255;
        int pj = j >> 9; int h2j = (j >> 8) & 1; int fj = j & 255;
        int pn = n >> 7; int h2n = (n >> 6) & 1; int e = n & 63;
        float v = 0.f;
        if (pj == pn && h2j == h2n)
            v = Wg2[(((pj * 2 + h2j) * 256) + fj) * 64 + e];
        d_W2bd[i] = v;
    }
    if (i < 1024) {
        int p = i >> 9; int r = i & 511; int h2 = r >> 8; int f = r & 255;
        d_bc1[i] = bg1[(p * 2 + h2) * 256 + f];
    }
    if (i < 256) {
        int p = i >> 7; int r = i & 127; int h2 = r >> 6; int e = r & 63;
        d_bc2[i] = bg2[(p * 2 + h2) * 64 + e];
    }
}

// ---------------------------------------------------------------------------
// tf32 mma.sync GEMM with 64x64 warp tiles.
// BM=128, BN=NT*32 (NT=8 -> 256, NT=4 -> 128), BK=32, 256 threads = 8 warps
// arranged 2(M) x 4(N); warp tile 64 x NT*8.
// A smem: SW128 m-major (128 rows x 32 tf32, 16B-quad XOR swizzle) ->
//   conflict-free frag LDS AND cp.async-compatible 16B chunks.
// B smem: k-major [32][BN+8] (bank = 8k+n, conflict-free).
// ADJ mode: A = pre-converted fp32 adjacency (exact 0/1 under tf32
//   truncation) loaded via cp.async, no register staging, no cvt.
// Dense mode: A register-staged with RNA tf32 rounding.
// B always register-staged with RNA tf32 rounding (precision).
// ---------------------------------------------------------------------------
template<int NT, bool ADJ, bool RELU, bool RES>
__global__ __launch_bounds__(256, 1)
void mma_gemm(const float* __restrict__ Av, int lda,
              const float* __restrict__ W, int ldw,
              const float* __restrict__ bias,
              const float* __restrict__ res, int ldres,
              float* __restrict__ C, int ldc,
              int Kd, int Nloc)
{
    constexpr int BN   = NT * 32;
    constexpr int BSTR = BN + 8;
    constexpr int ASZ  = 128 * 32;        // floats
    constexpr int BSZ  = 32 * BSTR;       // floats
    constexpr int STG  = ASZ + BSZ;

    extern __shared__ float smf[];

    const int tid  = threadIdx.x;
    const int lane = tid & 31;
    const int wid  = tid >> 5;
    const int warp_m = wid & 1;           // 2 warps over M (64 rows each)
    const int warp_n = wid >> 1;          // 4 warps over N (NT*8 cols each)
    const int bm = blockIdx.y * 128;
    const int bn = blockIdx.x * BN;

    const float* Ap;
    const float* Wp;
    float*       Cp;
    const float* bp = bias;
    const float* rp = res;

    if (ADJ) {
        const int z = blockIdx.z;
        const int p = z >> 4;
        const int b = z & 15;
        const int slice = p ? 4 : 1;
        Ap = Av + ((size_t)(b * 5 + slice)) * Kv * Kv;   // fp32 adjacency
        Wp = W + (size_t)b * Kv * ldw + p * Nloc;
        Cp = C + (size_t)b * Kv * ldc + p * Nloc;
        bp = bias + p * Nloc;
    } else {
        Ap = Av;
        Wp = W;
        Cp = C;
    }

    float* Abuf0 = smf;
    float* Bbuf0 = smf + ASZ;
    const uint32_t a_u32_0 = smem_to_u32(smf);

    // staging thread assignments
    const int brow = tid >> 3;            // 0..31 : B k-row
    const int bc0  = (tid & 7) * 4;       // B col chunk base

    float4 Areg[4];
    float4 Breg[NT];

    // ---- A issue (cp.async for ADJ, LDG->regs for dense) ----
    auto issueA = [&](int s, int k0) {
        if (ADJ) {
            uint32_t ab = a_u32_0 + s * (STG * 4);
            #pragma unroll
            for (int i = 0; i < 4; i++) {
                int chunk = i * 256 + tid;
                int r  = chunk >> 3;
                int kq = chunk & 7;
                const float* src = Ap + (size_t)(bm + r) * lda + k0 + kq * 4;
                uint32_t dst = ab + (r * 32 + ((kq ^ (r & 7)) << 2)) * 4;
                cp_async16(dst, src);
            }
            cp_commit();
        } else {
            #pragma unroll
            for (int i = 0; i < 4; i++) {
                int chunk = i * 256 + tid;
                int r  = chunk >> 3;
                int kq = chunk & 7;
                Areg[i] = *(const float4*)(Ap + (size_t)(bm + r) * lda + k0 + kq * 4);
            }
        }
    };
    auto stsA = [&](int s) {    // dense only
        float* ab = Abuf0 + s * STG;
        #pragma unroll
        for (int i = 0; i < 4; i++) {
            int chunk = i * 256 + tid;
            int r  = chunk >> 3;
            int kq = chunk & 7;
            uint4 v;
            v.x = f2tf(Areg[i].x); v.y = f2tf(Areg[i].y);
            v.z = f2tf(Areg[i].z); v.w = f2tf(Areg[i].w);
            *(uint4*)(ab + r * 32 + ((kq ^ (r & 7)) << 2)) = v;
        }
    };
    auto loadB = [&](int k0) {
        const float* wr = Wp + (size_t)(k0 + brow) * ldw + bn + bc0;
        #pragma unroll
        for (int u = 0; u < NT; u++)
            Breg[u] = *(const float4*)(wr + u * 32);
    };
    auto stsB = [&](int s) {
        float* bb = Bbuf0 + s * STG;
        #pragma unroll
        for (int u = 0; u < NT; u++) {
            uint4 v;
            v.x = f2tf(Breg[u].x); v.y = f2tf(Breg[u].y);
            v.z = f2tf(Breg[u].z); v.w = f2tf(Breg[u].w);
            *(uint4*)(bb + brow * BSTR + bc0 + u * 32) = v;
        }
    };

    float acc[4][NT][4] = {};

    // prologue: stage chunk 0
    issueA(0, 0);
    loadB(0);
    if (!ADJ) stsA(0);
    stsB(0);
    if (ADJ) cp_wait0();
    __syncthreads();

    const int nchunks = Kd >> 5;
    const int q  = lane & 3;
    const int rl = lane >> 2;

    for (int c = 0; c < nchunks; c++) {
        const int s = c & 1;
        const bool pf = (c + 1 < nchunks);
        if (pf) {
            issueA(s ^ 1, (c + 1) * 32);
            loadB((c + 1) * 32);
        }

        // ---- compute chunk s ----
        const float* Ab = Abuf0 + s * STG;
        const float* Bb = Bbuf0 + s * STG;
        #pragma unroll
        for (int kk = 0; kk < 4; kk++) {
            uint32_t af[4][4];
            uint32_t bf[NT][2];
            const int kq0 = kk * 2;
            #pragma unroll
            for (int mt = 0; mt < 4; mt++) {
                int r0 = warp_m * 64 + mt * 16 + rl;
                int r1 = r0 + 8;
                af[mt][0] = __float_as_uint(Ab[r0 * 32 + (((kq0    ) ^ (r0 & 7)) << 2) + q]);
                af[mt][1] = __float_as_uint(Ab[r1 * 32 + (((kq0    ) ^ (r1 & 7)) << 2) + q]);
                af[mt][2] = __float_as_uint(Ab[r0 * 32 + (((kq0 + 1) ^ (r0 & 7)) << 2) + q]);
                af[mt][3] = __float_as_uint(Ab[r1 * 32 + (((kq0 + 1) ^ (r1 & 7)) << 2) + q]);
            }
            const int kA = kk * 8 + q;
            #pragma unroll
            for (int nt = 0; nt < NT; nt++) {
                int cc = warp_n * (NT * 8) + nt * 8 + rl;
                bf[nt][0] = __float_as_uint(Bb[(kA    ) * BSTR + cc]);
                bf[nt][1] = __float_as_uint(Bb[(kA + 4) * BSTR + cc]);
            }
            #pragma unroll
            for (int mt = 0; mt < 4; mt++)
                #pragma unroll
                for (int nt = 0; nt < NT; nt++)
                    mma8(acc[mt][nt], af[mt], bf[nt]);
        }

        if (pf) {
            if (!ADJ) stsA(s ^ 1);
            stsB(s ^ 1);
            if (ADJ) cp_wait0();
            __syncthreads();
        }
    }

    // ---- epilogue ----
    #pragma unroll
    for (int mt = 0; mt < 4; mt++) {
        const int row = bm + warp_m * 64 + mt * 16 + rl;
        #pragma unroll
        for (int nt = 0; nt < NT; nt++) {
            const int col = bn + warp_n * (NT * 8) + nt * 8 + 2 * q;
            float b0 = 0.f, b1 = 0.f;
            if (bias) { b0 = bp[col]; b1 = bp[col + 1]; }
            float v0 = acc[mt][nt][0] + b0, v1 = acc[mt][nt][1] + b1;
            float v2 = acc[mt][nt][2] + b0, v3 = acc[mt][nt][3] + b1;
            if (RELU) {
                v0 = fmaxf(v0, 0.f); v1 = fmaxf(v1, 0.f);
                v2 = fmaxf(v2, 0.f); v3 = fmaxf(v3, 0.f);
            }
            if (RES) {
                const float* r0p = rp + (size_t)row * ldres + col;
                const float* r1p = rp + (size_t)(row + 8) * ldres + col;
                v0 += r0p[0]; v1 += r0p[1]; v2 += r1p[0]; v3 += r1p[1];
            }
            *(float2*)&Cp[(size_t)row * ldc + col] = make_float2(v0, v1);
            *(float2*)&Cp[(size_t)(row + 8) * ldc + col] = make_float2(v2, v3);
        }
    }
}

// ---------------------------------------------------------------------------
// LayerNorm (MWPToolkit: a*(x-mu)/(std_ddof1 + eps) + b) + residual
// ---------------------------------------------------------------------------
__global__ __launch_bounds__(256)
void ln_kernel(const float* __restrict__ x, const float* __restrict__ nodes,
               const float* __restrict__ ln_a, const float* __restrict__ ln_b,
               float* __restrict__ g)
{
    int warp = (blockIdx.x * blockDim.x + threadIdx.x) >> 5;
    int lane = threadIdx.x & 31;
    if (warp >= Mrows) return;
    const float* xr = x + (size_t)warp * 256;
    float v[8];
    float s = 0.f, ss = 0.f;
    #pragma unroll
    for (int j = 0; j < 8; j++) {
        v[j] = xr[lane + j * 32];
        s += v[j];
        ss += v[j] * v[j];
    }
    #pragma unroll
    for (int o = 16; o; o >>= 1) {
        s  += __shfl_xor_sync(0xffffffffu, s, o);
        ss += __shfl_xor_sync(0xffffffffu, ss, o);
    }
    float mu  = s * (1.f / 256.f);
    float var = (ss - 256.f * mu * mu) * (1.f / 255.f);
    float inv = 1.f / (sqrtf(fmaxf(var, 0.f)) + 1e-6f);
    const float* nd = nodes + (size_t)warp * 256;
    float* go = g + (size_t)warp * 256;
    #pragma unroll
    for (int j = 0; j < 8; j++) {
        int c = lane + j * 32;
        go[c] = ln_a[c] * (v[j] - mu) * inv + ln_b[c] + nd[c];
    }
}

// ---------------------------------------------------------------------------
// Launcher
// ---------------------------------------------------------------------------
extern "C" void kernel_launch(void* const* d_in, const int* in_sizes, int n_in,
                              void* d_out, int out_size)
{
    const float* nodes = (const float*)d_in[0];
    const int*   graph = (const int*)d_in[1];
    const float* Wg1   = (const float*)d_in[2];
    const float* bg1   = (const float*)d_in[3];
    const float* Wg2   = (const float*)d_in[4];
    const float* bg2   = (const float*)d_in[5];
    const float* Wf1   = (const float*)d_in[6];
    const float* bf1   = (const float*)d_in[7];
    const float* Wf2   = (const float*)d_in[8];
    const float* bf2   = (const float*)d_in[9];
    const float* ln_a  = (const float*)d_in[10];
    const float* ln_b  = (const float*)d_in[11];
    float* out = (float*)d_out;

    float *sup1, *h1, *sup2, *h2c, *g, *ff1, *Wc1, *W2bd, *bc1, *bc2;
    cudaGetSymbolAddress((void**)&sup1, d_sup1);
    cudaGetSymbolAddress((void**)&h1,   d_h1);
    cudaGetSymbolAddress((void**)&sup2, d_sup2);
    cudaGetSymbolAddress((void**)&h2c,  d_h2c);
    cudaGetSymbolAddress((void**)&g,    d_g);
    cudaGetSymbolAddress((void**)&ff1,  d_ff1);
    cudaGetSymbolAddress((void**)&Wc1,  d_Wc1);
    cudaGetSymbolAddress((void**)&W2bd, d_W2bd);
    cudaGetSymbolAddress((void**)&bc1,  d_bc1);
    cudaGetSymbolAddress((void**)&bc2,  d_bc2);

    // dynamic smem: 2 * (A 4096 + B 32*(BN+8)) floats
    const int SM8 = 2 * (4096 + 32 * (256 + 8)) * 4;   // 100,352 B
    const int SM4 = 2 * (4096 + 32 * (128 + 8)) * 4;   //  67,584 B
    cudaFuncSetAttribute(mma_gemm<8, false, false, false>,
                         cudaFuncAttributeMaxDynamicSharedMemorySize, SM8);
    cudaFuncSetAttribute(mma_gemm<8, true, true, false>,
                         cudaFuncAttributeMaxDynamicSharedMemorySize, SM8);
    cudaFuncSetAttribute(mma_gemm<4, true, false, false>,
                         cudaFuncAttributeMaxDynamicSharedMemorySize, SM4);
    cudaFuncSetAttribute(mma_gemm<8, false, true, false>,
                         cudaFuncAttributeMaxDynamicSharedMemorySize, SM8);
    cudaFuncSetAttribute(mma_gemm<8, false, false, true>,
                         cudaFuncAttributeMaxDynamicSharedMemorySize, SM8);

    // 0) adj passthrough (int -> float); output also serves as fp32 adjacency
    conv_adj<<<81920, 256>>>(graph, out, (int)(ADJ_ELEMS / 4));

    // 1) weight packing
    pack_w<<<1024, 256>>>(Wg1, bg1, Wg2, bg2);

    // 2) sup1 = nodes @ Wc1            (16384 x 256) @ (256 x 1024)
    mma_gemm<8, false, false, false><<<dim3(4, 128, 1), 256, SM8>>>(
        nodes, 256, Wc1, 1024, nullptr, nullptr, 0, sup1, 1024, 256, 0);

    // 3) h1 = relu(adj @ sup1 + bc1)   32 batches of (1024x1024)@(1024x512)
    mma_gemm<8, true, true, false><<<dim3(2, 8, 32), 256, SM8>>>(
        out, 1024, sup1, 1024, bc1, nullptr, 0, h1, 1024, 1024, 512);

    // 4) sup2 = h1 @ W2bd              (16384 x 1024) @ (1024 x 256) block-diag
    mma_gemm<8, false, false, false><<<dim3(1, 128, 1), 256, SM8>>>(
        h1, 1024, W2bd, 256, nullptr, nullptr, 0, sup2, 256, 1024, 0);

    // 5) h2 = adj @ sup2 + bc2         32 batches of (1024x1024)@(1024x128)
    mma_gemm<4, true, false, false><<<dim3(1, 8, 32), 256, SM4>>>(
        out, 1024, sup2, 256, bc2, nullptr, 0, h2c, 256, 1024, 128);

    // 6) g = LN(h2cat) + nodes
    ln_kernel<<<2048, 256>>>(h2c, nodes, ln_a, ln_b, g);

    // 7) ff1 = relu(g @ Wf1 + bf1)
    mma_gemm<8, false, true, false><<<dim3(1, 128, 1), 256, SM8>>>(
        g, 256, Wf1, 256, bf1, nullptr, 0, ff1, 256, 256, 0);

    // 8) out = ff1 @ Wf2 + bf2 + g
    mma_gemm<8, false, false, true><<<dim3(1, 128, 1), 256, SM8>>>(
        ff1, 256, Wf2, 256, bf2, g, 256, out + ADJ_ELEMS, 256, 256, 0);
}

// round 12
// speedup vs baseline: 2.7840x; 1.0242x over previous
#include <cuda_runtime.h>
#include <cstdint>

// ---------------------------------------------------------------------------
// Problem constants
// ---------------------------------------------------------------------------
#define Bv   16
#define Kv   1024
#define Mrows (Bv * Kv)            // 16384 rows of the token matrix

static const size_t ADJ_ELEMS = (size_t)Bv * 5 * Kv * Kv;   // 83,886,080

// ---------------------------------------------------------------------------
// Device scratch
// ---------------------------------------------------------------------------
__device__ float d_sup1[(size_t)Mrows * 1024];
__device__ float d_h1  [(size_t)Mrows * 1024];
__device__ float d_sup2[(size_t)Mrows * 256];
__device__ float d_h2c [(size_t)Mrows * 256];
__device__ float d_g   [(size_t)Mrows * 256];
__device__ float d_ff1 [(size_t)Mrows * 256];
__device__ float d_Wc1 [256 * 1024];   // packed layer-1 weights [k][p*512+h2*256+f]
__device__ float d_W2bd[1024 * 256];   // block-diagonal layer-2 weights
__device__ float d_bc1 [1024];
__device__ float d_bc2 [256];

// ---------------------------------------------------------------------------
// helpers
// ---------------------------------------------------------------------------
__device__ __forceinline__ uint32_t smem_to_u32(const void* p) {
    uint32_t a;
    asm("{ .reg .u64 t; cvta.to.shared.u64 t, %1; cvt.u32.u64 %0, t; }"
        : "=r"(a) : "l"(p));
    return a;
}

// tf32 rounding (RNA) so the MMA's truncating read is unbiased
__device__ __forceinline__ uint32_t f2tf(float x) {
    uint32_t r;
    asm("cvt.rna.tf32.f32 %0, %1;" : "=r"(r) : "f"(x));
    return r;
}

__device__ __forceinline__ void mma8(float* c, const uint32_t* a, const uint32_t* b) {
    asm volatile(
        "mma.sync.aligned.m16n8k8.row.col.f32.tf32.tf32.f32 "
        "{%0,%1,%2,%3},{%4,%5,%6,%7},{%8,%9},{%0,%1,%2,%3};"
        : "+f"(c[0]), "+f"(c[1]), "+f"(c[2]), "+f"(c[3])
        : "r"(a[0]), "r"(a[1]), "r"(a[2]), "r"(a[3]), "r"(b[0]), "r"(b[1]));
}

__device__ __forceinline__ void cp_async16(uint32_t dst, const void* src) {
    asm volatile("cp.async.ca.shared.global [%0], [%1], 16;"
                 :: "r"(dst), "l"(src) : "memory");
}
__device__ __forceinline__ void cp_commit() {
    asm volatile("cp.async.commit_group;" ::: "memory");
}
__device__ __forceinline__ void cp_wait2() {
    asm volatile("cp.async.wait_group 2;" ::: "memory");
}

// ---------------------------------------------------------------------------
// adj passthrough: int32 -> float32  (output doubles as fp32 adjacency source)
// ---------------------------------------------------------------------------
__global__ void conv_adj(const int* __restrict__ g, float* __restrict__ o, int n4) {
    int i = blockIdx.x * blockDim.x + threadIdx.x;
    if (i < n4) {
        int4 v = ((const int4*)g)[i];
        ((float4*)o)[i] = make_float4((float)v.x, (float)v.y, (float)v.z, (float)v.w);
    }
}

// ---------------------------------------------------------------------------
// Weight / bias packing: pair-fused layer-1 + block-diagonal layer-2
// ---------------------------------------------------------------------------
__global__ void pack_w(const float* __restrict__ Wg1, const float* __restrict__ bg1,
                       const float* __restrict__ Wg2, const float* __restrict__ bg2) {
    int i = blockIdx.x * blockDim.x + threadIdx.x;
    if (i < 256 * 1024) {
        int d = i >> 10;  int c = i & 1023;
        int p = c >> 9;   int r = c & 511;
        int h2 = r >> 8;  int f = r & 255;
        d_Wc1[i] = Wg1[(((p * 2 + h2) * 256) + d) * 256 + f];

        int j = i >> 8;  int n = i & 255;
        int pj = j >> 9; int h2j = (j >> 8) & 1; int fj = j & 255;
        int pn = n >> 7; int h2n = (n >> 6) & 1; int e = n & 63;
        float v = 0.f;
        if (pj == pn && h2j == h2n)
            v = Wg2[(((pj * 2 + h2j) * 256) + fj) * 64 + e];
        d_W2bd[i] = v;
    }
    if (i < 1024) {
        int p = i >> 9; int r = i & 511; int h2 = r >> 8; int f = r & 255;
        d_bc1[i] = bg1[(p * 2 + h2) * 256 + f];
    }
    if (i < 256) {
        int p = i >> 7; int r = i & 127; int h2 = r >> 6; int e = r & 63;
        d_bc2[i] = bg2[(p * 2 + h2) * 64 + e];
    }
}

// ---------------------------------------------------------------------------
// Adjacency GEMM, fully async: BM=128, BN=NT*32, BK=32, 256 threads,
// 8 warps 2(M) x 4(N), warp tile 64 x NT*8.  4-stage cp.async pipeline for
// BOTH operands; no register staging, no cvt, no STS in the mainloop.
// A = fp32 adjacency (exact 0/1 under tf32 truncation).
// B = sup1/sup2, pre-rounded to tf32 by the producing dense GEMM epilogue.
// ---------------------------------------------------------------------------
template<int NT, bool RELU>
__global__ __launch_bounds__(256, 1)
void adj_gemm_async(const float* __restrict__ Aall,
                    const float* __restrict__ W, int ldw,
                    const float* __restrict__ bias,
                    float* __restrict__ C, int ldc, int Nloc)
{
    constexpr int BN   = NT * 32;
    constexpr int BSTR = BN + 8;
    constexpr int ASZ  = 128 * 32;        // floats
    constexpr int BSZ  = 32 * BSTR;       // floats
    constexpr int STG  = ASZ + BSZ;

    extern __shared__ float smf[];
    const uint32_t sbase = smem_to_u32(smf);

    const int tid  = threadIdx.x;
    const int lane = tid & 31;
    const int wid  = tid >> 5;
    const int warp_m = wid & 1;
    const int warp_n = wid >> 1;
    const int bm = blockIdx.y * 128;
    const int bn = blockIdx.x * BN;

    const int z = blockIdx.z;
    const int p = z >> 4;
    const int b = z & 15;
    const int slice = p ? 4 : 1;
    const float* Ap = Aall + ((size_t)(b * 5 + slice)) * Kv * Kv;
    const float* Wp = W + (size_t)b * Kv * ldw + p * Nloc;
    float*       Cp = C + (size_t)b * Kv * ldc + p * Nloc;
    const float* bp = bias + p * Nloc;

    const int brow = tid >> 3;            // 0..31 : B k-row
    const int bc0  = (tid & 7) * 4;       // B col chunk base

    auto issue = [&](int s, int k0) {
        uint32_t ab = sbase + s * (STG * 4);
        #pragma unroll
        for (int i = 0; i < 4; i++) {
            int chunk = i * 256 + tid;
            int r  = chunk >> 3;
            int kq = chunk & 7;
            cp_async16(ab + (r * 32 + ((kq ^ (r & 7)) << 2)) * 4,
                       Ap + (size_t)(bm + r) * Kv + k0 + kq * 4);
        }
        uint32_t bb = ab + ASZ * 4;
        #pragma unroll
        for (int u = 0; u < NT; u++) {
            cp_async16(bb + (brow * BSTR + bc0 + u * 32) * 4,
                       Wp + (size_t)(k0 + brow) * ldw + bn + bc0 + u * 32);
        }
        cp_commit();
    };

    float acc[4][NT][4] = {};
    const int q  = lane & 3;
    const int rl = lane >> 2;

    constexpr int nchunks = Kv / 32;      // 32
    issue(0, 0);
    issue(1, 32);

    for (int c = 0; c < nchunks; c++) {
        if (c + 2 < nchunks) issue((c + 2) & 3, (c + 2) * 32);
        cp_wait2();
        __syncthreads();

        const float* Ab = smf + (c & 3) * STG;
        const float* Bb = Ab + ASZ;
        #pragma unroll
        for (int kk = 0; kk < 4; kk++) {
            uint32_t af[4][4];
            uint32_t bf[NT][2];
            const int kq0 = kk * 2;
            #pragma unroll
            for (int mt = 0; mt < 4; mt++) {
                int r0 = warp_m * 64 + mt * 16 + rl;
                int r1 = r0 + 8;
                af[mt][0] = __float_as_uint(Ab[r0 * 32 + (((kq0    ) ^ (r0 & 7)) << 2) + q]);
                af[mt][1] = __float_as_uint(Ab[r1 * 32 + (((kq0    ) ^ (r1 & 7)) << 2) + q]);
                af[mt][2] = __float_as_uint(Ab[r0 * 32 + (((kq0 + 1) ^ (r0 & 7)) << 2) + q]);
                af[mt][3] = __float_as_uint(Ab[r1 * 32 + (((kq0 + 1) ^ (r1 & 7)) << 2) + q]);
            }
            const int kA = kk * 8 + q;
            #pragma unroll
            for (int nt = 0; nt < NT; nt++) {
                int cc = warp_n * (NT * 8) + nt * 8 + rl;
                bf[nt][0] = __float_as_uint(Bb[(kA    ) * BSTR + cc]);
                bf[nt][1] = __float_as_uint(Bb[(kA + 4) * BSTR + cc]);
            }
            #pragma unroll
            for (int mt = 0; mt < 4; mt++)
                #pragma unroll
                for (int nt = 0; nt < NT; nt++)
                    mma8(acc[mt][nt], af[mt], bf[nt]);
        }
    }

    // ---- epilogue ----
    #pragma unroll
    for (int mt = 0; mt < 4; mt++) {
        const int row = bm + warp_m * 64 + mt * 16 + rl;
        #pragma unroll
        for (int nt = 0; nt < NT; nt++) {
            const int col = bn + warp_n * (NT * 8) + nt * 8 + 2 * q;
            float b0 = bp[col], b1 = bp[col + 1];
            float v0 = acc[mt][nt][0] + b0, v1 = acc[mt][nt][1] + b1;
            float v2 = acc[mt][nt][2] + b0, v3 = acc[mt][nt][3] + b1;
            if (RELU) {
                v0 = fmaxf(v0, 0.f); v1 = fmaxf(v1, 0.f);
                v2 = fmaxf(v2, 0.f); v3 = fmaxf(v3, 0.f);
            }
            *(float2*)&Cp[(size_t)row * ldc + col] = make_float2(v0, v1);
            *(float2*)&Cp[(size_t)(row + 8) * ldc + col] = make_float2(v2, v3);
        }
    }
}

// ---------------------------------------------------------------------------
// Dense tf32 GEMM (register-staged A/B with RNA rounding), 64x64 warp tiles.
// ROUND: round outputs to tf32 (RNA) so consumers can cp.async them directly.
// ---------------------------------------------------------------------------
template<int NT, bool RELU, bool RES, bool ROUND>
__global__ __launch_bounds__(256, 1)
void dense_gemm(const float* __restrict__ Av, int lda,
                const float* __restrict__ W, int ldw,
                const float* __restrict__ bias,
                const float* __restrict__ res, int ldres,
                float* __restrict__ C, int ldc,
                int Kd)
{
    constexpr int BN   = NT * 32;
    constexpr int BSTR = BN + 8;
    constexpr int ASZ  = 128 * 32;
    constexpr int BSZ  = 32 * BSTR;
    constexpr int STG  = ASZ + BSZ;

    extern __shared__ float smf[];

    const int tid  = threadIdx.x;
    const int lane = tid & 31;
    const int wid  = tid >> 5;
    const int warp_m = wid & 1;
    const int warp_n = wid >> 1;
    const int bm = blockIdx.y * 128;
    const int bn = blockIdx.x * BN;

    float* Abuf0 = smf;
    float* Bbuf0 = smf + ASZ;

    const int brow = tid >> 3;
    const int bc0  = (tid & 7) * 4;

    float4 Areg[4];
    float4 Breg[NT];

    auto ldgA = [&](int k0) {
        #pragma unroll
        for (int i = 0; i < 4; i++) {
            int chunk = i * 256 + tid;
            int r  = chunk >> 3;
            int kq = chunk & 7;
            Areg[i] = *(const float4*)(Av + (size_t)(bm + r) * lda + k0 + kq * 4);
        }
    };
    auto stsA = [&](int s) {
        float* ab = Abuf0 + s * STG;
        #pragma unroll
        for (int i = 0; i < 4; i++) {
            int chunk = i * 256 + tid;
            int r  = chunk >> 3;
            int kq = chunk & 7;
            uint4 v;
            v.x = f2tf(Areg[i].x); v.y = f2tf(Areg[i].y);
            v.z = f2tf(Areg[i].z); v.w = f2tf(Areg[i].w);
            *(uint4*)(ab + r * 32 + ((kq ^ (r & 7)) << 2)) = v;
        }
    };
    auto ldgB = [&](int k0) {
        const float* wr = W + (size_t)(k0 + brow) * ldw + bn + bc0;
        #pragma unroll
        for (int u = 0; u < NT; u++)
            Breg[u] = *(const float4*)(wr + u * 32);
    };
    auto stsB = [&](int s) {
        float* bb = Bbuf0 + s * STG;
        #pragma unroll
        for (int u = 0; u < NT; u++) {
            uint4 v;
            v.x = f2tf(Breg[u].x); v.y = f2tf(Breg[u].y);
            v.z = f2tf(Breg[u].z); v.w = f2tf(Breg[u].w);
            *(uint4*)(bb + brow * BSTR + bc0 + u * 32) = v;
        }
    };

    float acc[4][NT][4] = {};

    ldgA(0);
    ldgB(0);
    stsA(0);
    stsB(0);
    __syncthreads();

    const int nchunks = Kd >> 5;
    const int q  = lane & 3;
    const int rl = lane >> 2;

    for (int c = 0; c < nchunks; c++) {
        const int s = c & 1;
        const bool pf = (c + 1 < nchunks);
        if (pf) {
            ldgA((c + 1) * 32);
            ldgB((c + 1) * 32);
        }

        const float* Ab = Abuf0 + s * STG;
        const float* Bb = Bbuf0 + s * STG;
        #pragma unroll
        for (int kk = 0; kk < 4; kk++) {
            uint32_t af[4][4];
            uint32_t bf[NT][2];
            const int kq0 = kk * 2;
            #pragma unroll
            for (int mt = 0; mt < 4; mt++) {
                int r0 = warp_m * 64 + mt * 16 + rl;
                int r1 = r0 + 8;
                af[mt][0] = __float_as_uint(Ab[r0 * 32 + (((kq0    ) ^ (r0 & 7)) << 2) + q]);
                af[mt][1] = __float_as_uint(Ab[r1 * 32 + (((kq0    ) ^ (r1 & 7)) << 2) + q]);
                af[mt][2] = __float_as_uint(Ab[r0 * 32 + (((kq0 + 1) ^ (r0 & 7)) << 2) + q]);
                af[mt][3] = __float_as_uint(Ab[r1 * 32 + (((kq0 + 1) ^ (r1 & 7)) << 2) + q]);
            }
            const int kA = kk * 8 + q;
            #pragma unroll
            for (int nt = 0; nt < NT; nt++) {
                int cc = warp_n * (NT * 8) + nt * 8 + rl;
                bf[nt][0] = __float_as_uint(Bb[(kA    ) * BSTR + cc]);
                bf[nt][1] = __float_as_uint(Bb[(kA + 4) * BSTR + cc]);
            }
            #pragma unroll
            for (int mt = 0; mt < 4; mt++)
                #pragma unroll
                for (int nt = 0; nt < NT; nt++)
                    mma8(acc[mt][nt], af[mt], bf[nt]);
        }

        if (pf) {
            stsA(s ^ 1);
            stsB(s ^ 1);
            __syncthreads();
        }
    }

    #pragma unroll
    for (int mt = 0; mt < 4; mt++) {
        const int row = bm + warp_m * 64 + mt * 16 + rl;
        #pragma unroll
        for (int nt = 0; nt < NT; nt++) {
            const int col = bn + warp_n * (NT * 8) + nt * 8 + 2 * q;
            float b0 = 0.f, b1 = 0.f;
            if (bias) { b0 = bias[col]; b1 = bias[col + 1]; }
            float v0 = acc[mt][nt][0] + b0, v1 = acc[mt][nt][1] + b1;
            float v2 = acc[mt][nt][2] + b0, v3 = acc[mt][nt][3] + b1;
            if (RELU) {
                v0 = fmaxf(v0, 0.f); v1 = fmaxf(v1, 0.f);
                v2 = fmaxf(v2, 0.f); v3 = fmaxf(v3, 0.f);
            }
            if (RES) {
                const float* r0p = res + (size_t)row * ldres + col;
                const float* r1p = res + (size_t)(row + 8) * ldres + col;
                v0 += r0p[0]; v1 += r0p[1]; v2 += r1p[0]; v3 += r1p[1];
            }
            if (ROUND) {
                v0 = __uint_as_float(f2tf(v0)); v1 = __uint_as_float(f2tf(v1));
                v2 = __uint_as_float(f2tf(v2)); v3 = __uint_as_float(f2tf(v3));
            }
            *(float2*)&C[(size_t)row * ldc + col] = make_float2(v0, v1);
            *(float2*)&C[(size_t)(row + 8) * ldc + col] = make_float2(v2, v3);
        }
    }
}

// ---------------------------------------------------------------------------
// LayerNorm (MWPToolkit: a*(x-mu)/(std_ddof1 + eps) + b) + residual
// ---------------------------------------------------------------------------
__global__ __launch_bounds__(256)
void ln_kernel(const float* __restrict__ x, const float* __restrict__ nodes,
               const float* __restrict__ ln_a, const float* __restrict__ ln_b,
               float* __restrict__ g)
{
    int warp = (blockIdx.x * blockDim.x + threadIdx.x) >> 5;
    int lane = threadIdx.x & 31;
    if (warp >= Mrows) return;
    const float* xr = x + (size_t)warp * 256;
    float v[8];
    float s = 0.f, ss = 0.f;
    #pragma unroll
    for (int j = 0; j < 8; j++) {
        v[j] = xr[lane + j * 32];
        s += v[j];
        ss += v[j] * v[j];
    }
    #pragma unroll
    for (int o = 16; o; o >>= 1) {
        s  += __shfl_xor_sync(0xffffffffu, s, o);
        ss += __shfl_xor_sync(0xffffffffu, ss, o);
    }
    float mu  = s * (1.f / 256.f);
    float var = (ss - 256.f * mu * mu) * (1.f / 255.f);
    float inv = 1.f / (sqrtf(fmaxf(var, 0.f)) + 1e-6f);
    const float* nd = nodes + (size_t)warp * 256;
    float* go = g + (size_t)warp * 256;
    #pragma unroll
    for (int j = 0; j < 8; j++) {
        int c = lane + j * 32;
        go[c] = ln_a[c] * (v[j] - mu) * inv + ln_b[c] + nd[c];
    }
}

// ---------------------------------------------------------------------------
// Launcher
// ---------------------------------------------------------------------------
extern "C" void kernel_launch(void* const* d_in, const int* in_sizes, int n_in,
                              void* d_out, int out_size)
{
    const float* nodes = (const float*)d_in[0];
    const int*   graph = (const int*)d_in[1];
    const float* Wg1   = (const float*)d_in[2];
    const float* bg1   = (const float*)d_in[3];
    const float* Wg2   = (const float*)d_in[4];
    const float* bg2   = (const float*)d_in[5];
    const float* Wf1   = (const float*)d_in[6];
    const float* bf1   = (const float*)d_in[7];
    const float* Wf2   = (const float*)d_in[8];
    const float* bf2   = (const float*)d_in[9];
    const float* ln_a  = (const float*)d_in[10];
    const float* ln_b  = (const float*)d_in[11];
    float* out = (float*)d_out;

    float *sup1, *h1, *sup2, *h2c, *g, *ff1, *Wc1, *W2bd, *bc1, *bc2;
    cudaGetSymbolAddress((void**)&sup1, d_sup1);
    cudaGetSymbolAddress((void**)&h1,   d_h1);
    cudaGetSymbolAddress((void**)&sup2, d_sup2);
    cudaGetSymbolAddress((void**)&h2c,  d_h2c);
    cudaGetSymbolAddress((void**)&g,    d_g);
    cudaGetSymbolAddress((void**)&ff1,  d_ff1);
    cudaGetSymbolAddress((void**)&Wc1,  d_Wc1);
    cudaGetSymbolAddress((void**)&W2bd, d_W2bd);
    cudaGetSymbolAddress((void**)&bc1,  d_bc1);
    cudaGetSymbolAddress((void**)&bc2,  d_bc2);

    const int STG8 = (128 * 32 + 32 * (256 + 8)) * 4;   // 50,176 B
    const int STG4 = (128 * 32 + 32 * (128 + 8)) * 4;   // 33,792 B
    const int ADJ8 = 4 * STG8;                          // 200,704 B
    const int ADJ4 = 4 * STG4;                          // 135,168 B
    const int DEN8 = 2 * STG8;                          // 100,352 B
    cudaFuncSetAttribute(adj_gemm_async<8, true>,
                         cudaFuncAttributeMaxDynamicSharedMemorySize, ADJ8);
    cudaFuncSetAttribute(adj_gemm_async<4, false>,
                         cudaFuncAttributeMaxDynamicSharedMemorySize, ADJ4);
    cudaFuncSetAttribute(dense_gemm<8, false, false, true>,
                         cudaFuncAttributeMaxDynamicSharedMemorySize, DEN8);
    cudaFuncSetAttribute(dense_gemm<8, true, false, false>,
                         cudaFuncAttributeMaxDynamicSharedMemorySize, DEN8);
    cudaFuncSetAttribute(dense_gemm<8, false, true, false>,
                         cudaFuncAttributeMaxDynamicSharedMemorySize, DEN8);

    // 0) adj passthrough (int -> float); output also serves as fp32 adjacency
    conv_adj<<<81920, 256>>>(graph, out, (int)(ADJ_ELEMS / 4));

    // 1) weight packing
    pack_w<<<1024, 256>>>(Wg1, bg1, Wg2, bg2);

    // 2) sup1 = nodes @ Wc1 (tf32-rounded output)   (16384x256)@(256x1024)
    dense_gemm<8, false, false, true><<<dim3(4, 128, 1), 256, DEN8>>>(
        nodes, 256, Wc1, 1024, nullptr, nullptr, 0, sup1, 1024, 256);

    // 3) h1 = relu(adj @ sup1 + bc1)   32 batches of (1024x1024)@(1024x512)
    adj_gemm_async<8, true><<<dim3(2, 8, 32), 256, ADJ8>>>(
        out, sup1, 1024, bc1, h1, 1024, 512);

    // 4) sup2 = h1 @ W2bd (tf32-rounded output)     (16384x1024)@(1024x256)
    dense_gemm<8, false, false, true><<<dim3(1, 128, 1), 256, DEN8>>>(
        h1, 1024, W2bd, 256, nullptr, nullptr, 0, sup2, 256, 1024);

    // 5) h2 = adj @ sup2 + bc2         32 batches of (1024x1024)@(1024x128)
    adj_gemm_async<4, false><<<dim3(1, 8, 32), 256, ADJ4>>>(
        out, sup2, 256, bc2, h2c, 256, 128);

    // 6) g = LN(h2cat) + nodes
    ln_kernel<<<2048, 256>>>(h2c, nodes, ln_a, ln_b, g);

    // 7) ff1 = relu(g @ Wf1 + bf1)
    dense_gemm<8, true, false, false><<<dim3(1, 128, 1), 256, DEN8>>>(
        g, 256, Wf1, 256, bf1, nullptr, 0, ff1, 256, 256);

    // 8) out = ff1 @ Wf2 + bf2 + g
    dense_gemm<8, false, true, false><<<dim3(1, 128, 1), 256, DEN8>>>(
        ff1, 256, Wf2, 256, bf2, g, 256, out + ADJ_ELEMS, 256, 256);
}